// round 13
// baseline (speedup 1.0000x reference)
#include <cuda_runtime.h>
#include <cuda_fp16.h>
#include <cstdint>
#include <cstddef>

#define TPB   128
#define NKEY  127
#define NH    4
#define DK    64
#define DOUT  256
#define STRH  80    // fp16 row stride in halves (160B = 40 words)
#define STGF  68    // fp32 staging row stride in floats

static constexpr int OFFB_STG  = 0;
static constexpr int OFFB_KV16 = OFFB_STG  + 128 * STGF * 4;   // 34816
static constexpr int OFFB_WK16 = OFFB_KV16 + 128 * STRH * 2;   // +20480
static constexpr int OFFB_QB   = OFFB_WK16 + 256 * STRH * 2;   // +40960
static constexpr int OFFB_WS   = OFFB_QB + DOUT * 4;
static constexpr int OFFB_SC   = OFFB_WS + DK * 4;             // [4][128]
static constexpr int OFFB_W    = OFFB_SC + NH * 128 * 4;       // [128][4]
static constexpr int OFFB_WV   = OFFB_W + 128 * NH * 4;        // [256]
static constexpr int OFFB_PART = OFFB_WV + DOUT * 4;           // [256][5]
static constexpr int OFFB_BS   = OFFB_PART + DOUT * 5 * 4;
static constexpr int OFFB_NXT  = OFFB_BS + 16;
static constexpr int SMEM_BYTES = OFFB_NXT + 16;               // ~105.4 KB

__device__ float g_qb[4096 * 256];   // qb for all tiles (16 MB budget, static)
__device__ int   g_ctr;              // work-steal counter

__device__ __forceinline__ float tanh_fast(float x) {
    float y;
    asm("tanh.approx.f32 %0, %1;" : "=f"(y) : "f"(x));
    return y;
}
__device__ __forceinline__ uint32_t f2h2(float a, float b) {
    __half2 h = __floats2half2_rn(a, b);
    return *(uint32_t*)&h;
}

// m16n8k16 fp16 MMA, row(A) x col(B), fp32 accumulate (arch-neutral PTX)
__device__ __forceinline__ void mma16(float& d0, float& d1, float& d2,
                                      float& d3, uint32_t a0, uint32_t a1,
                                      uint32_t a2, uint32_t a3,
                                      uint32_t b0, uint32_t b1) {
    asm volatile(
        "mma.sync.aligned.m16n8k16.row.col.f32.f16.f16.f32 "
        "{%0,%1,%2,%3}, {%4,%5,%6,%7}, {%8,%9}, {%0,%1,%2,%3};"
        : "+f"(d0), "+f"(d1), "+f"(d2), "+f"(d3)
        : "r"(a0), "r"(a1), "r"(a2), "r"(a3), "r"(b0), "r"(b1));
}

#define CP_ASYNC16(sdst, gsrc)                                                \
    asm volatile("cp.async.cg.shared.global [%0], [%1], 16;"                  \
                 :: "r"(sdst), "l"(gsrc))
#define CP_COMMIT() asm volatile("cp.async.commit_group;")
#define CP_WAIT0()  asm volatile("cp.async.wait_group 0;")

__device__ __forceinline__ void prefetch_kv(const float* __restrict__ gsrc,
                                            float* stg) {
    #pragma unroll 1
    for (int j = threadIdx.x; j < NKEY * 16; j += TPB) {
        int row = j >> 4;
        int c4  = j & 15;
        unsigned sa =
            (unsigned)__cvta_generic_to_shared(stg + row * STGF + c4 * 4);
        CP_ASYNC16(sa, gsrc + j * 4);
    }
}

// ---- prologue kernel: reset counter + qb for all tiles ----
__global__ void __launch_bounds__(256, 4)
qb_kernel(const float* __restrict__ q_x, const float* __restrict__ Wq,
          const float* __restrict__ bias, int BT)
{
    __shared__ float s_q[8 * DK];
    const int tid = threadIdx.x;
    const int bt0 = blockIdx.x * 8;
    if (blockIdx.x == 0 && tid == 0) g_ctr = 0;

    #pragma unroll 2
    for (int idx = tid; idx < 8 * DK; idx += 256) {
        int t = idx >> 6, k = idx & 63;
        int bt = bt0 + t;
        s_q[idx] = (bt < BT) ? q_x[(size_t)bt * DK + k] : 0.f;
    }
    __syncthreads();

    float4 wq[16];
    const float4* wq4 = (const float4*)(Wq + tid * DK);
    #pragma unroll
    for (int i = 0; i < 16; i++) wq[i] = __ldg(wq4 + i);
    const float bb = __ldg(bias + (tid & (DK - 1)));

    #pragma unroll 1
    for (int j = 0; j < 8; ++j) {
        int bt = bt0 + j;
        if (bt >= BT) break;
        const float* qq = s_q + j * DK;
        float a0 = 0.f, a1 = 0.f, a2 = 0.f, a3 = 0.f;
        #pragma unroll
        for (int i = 0; i < 16; i++) {
            a0 = fmaf(qq[4 * i + 0], wq[i].x, a0);
            a1 = fmaf(qq[4 * i + 1], wq[i].y, a1);
            a2 = fmaf(qq[4 * i + 2], wq[i].z, a2);
            a3 = fmaf(qq[4 * i + 3], wq[i].w, a3);
        }
        g_qb[(size_t)bt * DOUT + tid] = (a0 + a1) + (a2 + a3) + bb;
    }
}

__global__ void __launch_bounds__(TPB, 2)
raamh_kernel(const float* __restrict__ kv_x, const float* __restrict__ Wk,
             const float* __restrict__ Wv,  const float* __restrict__ Ws,
             const float* __restrict__ bs,  float* __restrict__ out, int BT)
{
    extern __shared__ char smem[];
    float*  s_stg  = (float*) (smem + OFFB_STG);
    __half* s_kvh  = (__half*)(smem + OFFB_KV16);
    __half* s_wkh  = (__half*)(smem + OFFB_WK16);
    float*  s_qb   = (float*) (smem + OFFB_QB);
    float*  s_ws   = (float*) (smem + OFFB_WS);
    float*  s_sc   = (float*) (smem + OFFB_SC);
    float*  s_w    = (float*) (smem + OFFB_W);
    float*  s_wv   = (float*) (smem + OFFB_WV);
    float*  s_part = (float*) (smem + OFFB_PART);
    float*  s_bs   = (float*) (smem + OFFB_BS);
    int*    s_nxt  = (int*)   (smem + OFFB_NXT);

    const int tid  = threadIdx.x;
    const int lane = tid & 31;
    const int wrp  = tid >> 5;       // warp's head
    const int g    = lane >> 2;
    const int tg   = lane & 3;

    // ---- one-time staging: Wk -> fp16, ws, bs, zero kv row 127 ----
    {
        #pragma unroll 1
        for (int j = tid; j < DOUT * 16; j += TPB) {
            int row = j >> 4, c4 = (j & 15) * 4;
            float4 v = __ldg((const float4*)(Wk + row * DK + c4));
            uint2 hh = make_uint2(f2h2(v.x, v.y), f2h2(v.z, v.w));
            *(uint2*)(s_wkh + row * STRH + c4) = hh;
        }
        if (tid < DK) s_ws[tid] = Ws[tid];
        if (tid == 0) {
            s_bs[0] = bs[0];
            s_nxt[0] = atomicAdd(&g_ctr, 1);
        }
        if (tid < 16) {
            uint2 z = make_uint2(0u, 0u);
            *(uint2*)(s_kvh + 127 * STRH + tid * 4) = z;
        }
    }
    __syncthreads();

    int cur = s_nxt[0];
    if (cur >= BT) return;
    prefetch_kv(kv_x + (size_t)cur * (NKEY * DK), s_stg);
    CP_COMMIT();

    while (true) {
        if (tid == 0) s_nxt[0] = atomicAdd(&g_ctr, 1);
        CP_WAIT0();
        __syncthreads();           // staging ready; prior tile consumed

        // ---- convert staging -> fp16 kv; stage qb slice ----
        if (tid < NKEY) {
            const float* src = s_stg + tid * STGF;
            __half* dst = s_kvh + tid * STRH;
            #pragma unroll
            for (int u = 0; u < 16; ++u) {
                float4 v = *(const float4*)(src + u * 4);
                uint2 hh = make_uint2(f2h2(v.x, v.y), f2h2(v.z, v.w));
                *(uint2*)(dst + u * 4) = hh;
            }
        }
        {
            const float* qsrc = g_qb + (size_t)cur * DOUT;
            s_qb[tid]       = __ldg(qsrc + tid);
            s_qb[tid + 128] = __ldg(qsrc + tid + 128);
        }
        __syncthreads();           // kv16 + qb ready; staging free

        const int nxt = s_nxt[0];
        if (nxt < BT) {
            prefetch_kv(kv_x + (size_t)nxt * (NKEY * DK), s_stg);
            CP_COMMIT();
        }

        const float bsv = s_bs[0];
        const int head = wrp;
        const __half* wkp = s_wkh + (head * 64) * STRH;

        // ---- score GEMM: fp16 m16n8k16; warp = head, 4 nh tasks ----
        #pragma unroll 1
        for (int nh = 0; nh < 4; ++nh) {
            const __half* kvp = s_kvh + (nh * 32) * STRH;

            float acc[2][8][4];
            #pragma unroll
            for (int mb = 0; mb < 2; ++mb)
                #pragma unroll
                for (int nb = 0; nb < 8; ++nb)
                    #pragma unroll
                    for (int c = 0; c < 4; ++c) acc[mb][nb][c] = 0.f;

            #pragma unroll
            for (int kc = 0; kc < 4; ++kc) {
                const int ho = kc * 16 + 4 * tg;   // permuted k slots
                uint2 u[2], v[2];
                #pragma unroll
                for (int mb = 0; mb < 2; ++mb) {
                    const __half* ar = kvp + (mb * 16 + g) * STRH + ho;
                    u[mb] = *(const uint2*)ar;
                    v[mb] = *(const uint2*)(ar + 8 * STRH);
                }
                #pragma unroll
                for (int nb = 0; nb < 8; ++nb) {
                    uint2 w = *(const uint2*)(wkp + (nb * 8 + g) * STRH + ho);
                    #pragma unroll
                    for (int mb = 0; mb < 2; ++mb)
                        mma16(acc[mb][nb][0], acc[mb][nb][1],
                              acc[mb][nb][2], acc[mb][nb][3],
                              u[mb].x, v[mb].x, u[mb].y, v[mb].y,
                              w.x, w.y);
                }
            }

            // epilogue: tanh + Ws reduction over this head's 64 o
            float part[2][2];
            part[0][0] = part[0][1] = part[1][0] = part[1][1] = 0.f;
            #pragma unroll
            for (int nb = 0; nb < 8; ++nb) {
                #pragma unroll
                for (int cc = 0; cc < 2; ++cc) {
                    const int k = nb * 8 + tg * 2 + cc;
                    const float wsk = s_ws[k];
                    const float qbo = s_qb[head * 64 + k];
                    #pragma unroll
                    for (int mb = 0; mb < 2; ++mb) {
                        part[mb][0] = fmaf(
                            wsk, tanh_fast(acc[mb][nb][cc] + qbo),
                            part[mb][0]);
                        part[mb][1] = fmaf(
                            wsk, tanh_fast(acc[mb][nb][2 + cc] + qbo),
                            part[mb][1]);
                    }
                }
            }
            #pragma unroll
            for (int m = 1; m <= 2; m <<= 1) {
                #pragma unroll
                for (int mb = 0; mb < 2; ++mb) {
                    part[mb][0] += __shfl_xor_sync(0xffffffffu, part[mb][0], m);
                    part[mb][1] += __shfl_xor_sync(0xffffffffu, part[mb][1], m);
                }
            }
            if (tg == 0) {
                #pragma unroll
                for (int mb = 0; mb < 2; ++mb) {
                    const int r = nh * 32 + mb * 16 + g;
                    s_sc[head * 128 + r]     = part[mb][0] + bsv;
                    s_sc[head * 128 + r + 8] = part[mb][1] + bsv;
                }
            }
        }
        __syncwarp();              // s_sc produced/consumed by same warp

        // ---- softmax per head (warp per head), n-major s_w ----
        {
            int hh = wrp;
            int ln = lane;
            const float* sc = s_sc + hh * 128;
            float v0 = sc[ln];
            float v1 = sc[ln + 32];
            float v2 = sc[ln + 64];
            float v3 = (ln + 96 < NKEY) ? sc[ln + 96] : -1e30f;
            float m = fmaxf(fmaxf(v0, v1), fmaxf(v2, v3));
            #pragma unroll
            for (int o = 16; o > 0; o >>= 1)
                m = fmaxf(m, __shfl_xor_sync(0xffffffffu, m, o));
            float e0 = __expf(v0 - m);
            float e1 = __expf(v1 - m);
            float e2 = __expf(v2 - m);
            float e3 = (ln + 96 < NKEY) ? __expf(v3 - m) : 0.f;
            float s = (e0 + e1) + (e2 + e3);
            #pragma unroll
            for (int o = 16; o > 0; o >>= 1)
                s += __shfl_xor_sync(0xffffffffu, s, o);
            float inv = 1.f / s;
            s_w[ln * 4 + hh]        = e0 * inv;
            s_w[(ln + 32) * 4 + hh] = e1 * inv;
            s_w[(ln + 64) * 4 + hh] = e2 * inv;
            if (ln + 96 < NKEY) s_w[(ln + 96) * 4 + hh] = e3 * inv;
        }
        __syncthreads();

        // ---- weighted kv sum: thread = (col pair, n-group) ----
        {
            const int cp = tid & 31;
            const int ng = tid >> 5;
            const int n0 = ng * 32;
            const int n1 = (ng == 3) ? NKEY : n0 + 32;
            float ax[4] = {0.f, 0.f, 0.f, 0.f};
            float ay[4] = {0.f, 0.f, 0.f, 0.f};
            #pragma unroll 4
            for (int n = n0; n < n1; ++n) {
                __half2 h2 = *(const __half2*)(s_kvh + n * STRH + 2 * cp);
                float2 f = __half22float2(h2);
                float4 w4 = *(const float4*)(s_w + n * 4);
                ax[0] = fmaf(w4.x, f.x, ax[0]);
                ax[1] = fmaf(w4.y, f.x, ax[1]);
                ax[2] = fmaf(w4.z, f.x, ax[2]);
                ax[3] = fmaf(w4.w, f.x, ax[3]);
                ay[0] = fmaf(w4.x, f.y, ay[0]);
                ay[1] = fmaf(w4.y, f.y, ay[1]);
                ay[2] = fmaf(w4.z, f.y, ay[2]);
                ay[3] = fmaf(w4.w, f.y, ay[3]);
            }
            #pragma unroll
            for (int hh = 0; hh < 4; ++hh) {
                s_part[(hh * 64 + 2 * cp) * 5 + ng]     = ax[hh];
                s_part[(hh * 64 + 2 * cp + 1) * 5 + ng] = ay[hh];
            }
        }
        __syncthreads();
        #pragma unroll
        for (int rep = 0; rep < 2; ++rep) {
            const int o = tid + rep * 128;
            const float* p = s_part + o * 5;
            s_wv[o] = (p[0] + p[1]) + (p[2] + p[3]);
        }
        __syncthreads();

        // ---- output projection: thread covers o = tid, tid+128 ----
        #pragma unroll 1
        for (int rep = 0; rep < 2; ++rep) {
            const int o = tid + rep * 128;
            const float* wvh = s_wv + (o >> 6) * 64;
            const float4* wv4 = (const float4*)(Wv + o * DK);
            float a0 = 0.f, a1 = 0.f, a2 = 0.f, a3 = 0.f;
            #pragma unroll
            for (int i = 0; i < 16; i++) {
                float4 w = __ldg(wv4 + i);
                a0 = fmaf(wvh[4 * i + 0], w.x, a0);
                a1 = fmaf(wvh[4 * i + 1], w.y, a1);
                a2 = fmaf(wvh[4 * i + 2], w.z, a2);
                a3 = fmaf(wvh[4 * i + 3], w.w, a3);
            }
            out[(size_t)cur * DOUT + o] = (a0 + a1) + (a2 + a3);
        }

        if (nxt >= BT) break;
        cur = nxt;
    }
}

extern "C" void kernel_launch(void* const* d_in, const int* in_sizes, int n_in,
                              void* d_out, int out_size) {
    (void)n_in; (void)out_size;
    const float* q_x  = (const float*)d_in[0];
    const float* kv_x = (const float*)d_in[1];
    const float* Wk   = (const float*)d_in[2];
    const float* Wq   = (const float*)d_in[3];
    const float* Wv   = (const float*)d_in[4];
    const float* bias = (const float*)d_in[5];
    const float* Ws   = (const float*)d_in[6];
    const float* bs   = (const float*)d_in[7];
    float* out = (float*)d_out;

    const int BT = in_sizes[0] / DK;

    // prologue: counter reset + qb precompute
    int gridA = (BT + 7) / 8;
    qb_kernel<<<gridA, 256>>>(q_x, Wq, bias, BT);

    int grid = 2 * 152;
    if (grid > BT) grid = BT;

    cudaFuncSetAttribute(raamh_kernel,
                         cudaFuncAttributeMaxDynamicSharedMemorySize,
                         SMEM_BYTES);
    raamh_kernel<<<grid, TPB, SMEM_BYTES>>>(kv_x, Wk, Wv, Ws, bs, out, BT);
}

// round 14
// speedup vs baseline: 1.0893x; 1.0893x over previous
#include <cuda_runtime.h>
#include <cuda_fp16.h>
#include <cstdint>
#include <cstddef>

#define TPB   128
#define NKEY  127
#define NH    4
#define DK    64
#define DOUT  256
#define STRH  80    // fp16 kv/wk row stride in halves (160B)
#define STRW  136   // fp16 w row stride in halves (272B) -> conflict-free A frags
#define STGF  68    // fp32 staging row stride in floats
#define MAXT  4

static constexpr int OFFB_STG  = 0;
static constexpr int OFFB_KV16 = OFFB_STG  + 128 * STGF * 4;   // 34816
static constexpr int OFFB_WK16 = OFFB_KV16 + 128 * STRH * 2;   // 55296
static constexpr int OFFB_QBA  = OFFB_WK16 + 256 * STRH * 2;   // 96256
static constexpr int OFFB_QT   = OFFB_QBA + MAXT * DOUT * 4;   // 100352
static constexpr int OFFB_WS   = OFFB_QT + MAXT * DK * 4;      // 101376
static constexpr int OFFB_SC   = OFFB_WS + DK * 4;             // 101632
static constexpr int OFFB_W16  = OFFB_SC + NH * 128 * 4;       // 103680 [16][136] fp16
static constexpr int OFFB_WV   = OFFB_W16 + 16 * STRW * 2;     // 108032 [256] f32
static constexpr int OFFB_BS   = OFFB_WV + DOUT * 4;           // 109056
static constexpr int SMEM_BYTES = OFFB_BS + 16;                // 109072 (x2 = 218K)

__device__ __forceinline__ float tanh_fast(float x) {
    float y;
    asm("tanh.approx.f32 %0, %1;" : "=f"(y) : "f"(x));
    return y;
}
__device__ __forceinline__ uint32_t f2h2(float a, float b) {
    __half2 h = __floats2half2_rn(a, b);
    return *(uint32_t*)&h;
}

// m16n8k16 fp16 MMA, row(A) x col(B), fp32 accumulate (arch-neutral PTX)
__device__ __forceinline__ void mma16(float& d0, float& d1, float& d2,
                                      float& d3, uint32_t a0, uint32_t a1,
                                      uint32_t a2, uint32_t a3,
                                      uint32_t b0, uint32_t b1) {
    asm volatile(
        "mma.sync.aligned.m16n8k16.row.col.f32.f16.f16.f32 "
        "{%0,%1,%2,%3}, {%4,%5,%6,%7}, {%8,%9}, {%0,%1,%2,%3};"
        : "+f"(d0), "+f"(d1), "+f"(d2), "+f"(d3)
        : "r"(a0), "r"(a1), "r"(a2), "r"(a3), "r"(b0), "r"(b1));
}

// ldmatrix x2 transposed b16: B fragment from row-major [K,N] memory
__device__ __forceinline__ void ldmx2t(uint32_t& r0, uint32_t& r1,
                                       uint32_t saddr) {
    asm volatile(
        "ldmatrix.sync.aligned.m8n8.x2.trans.shared.b16 {%0,%1}, [%2];"
        : "=r"(r0), "=r"(r1) : "r"(saddr));
}

#define CP_ASYNC16(sdst, gsrc)                                                \
    asm volatile("cp.async.cg.shared.global [%0], [%1], 16;"                  \
                 :: "r"(sdst), "l"(gsrc))
#define CP_COMMIT() asm volatile("cp.async.commit_group;")
#define CP_WAIT0()  asm volatile("cp.async.wait_group 0;")

__device__ __forceinline__ void prefetch_kv(const float* __restrict__ gsrc,
                                            float* stg) {
    #pragma unroll 1
    for (int j = threadIdx.x; j < NKEY * 16; j += TPB) {
        int row = j >> 4;
        int c4  = j & 15;
        unsigned sa =
            (unsigned)__cvta_generic_to_shared(stg + row * STGF + c4 * 4);
        CP_ASYNC16(sa, gsrc + j * 4);
    }
}

__global__ void __launch_bounds__(TPB, 2)
raamh_kernel(const float* __restrict__ q_x, const float* __restrict__ kv_x,
             const float* __restrict__ Wk,  const float* __restrict__ Wq,
             const float* __restrict__ Wv,  const float* __restrict__ bias,
             const float* __restrict__ Ws,  const float* __restrict__ bs,
             float* __restrict__ out, int BT)
{
    extern __shared__ char smem[];
    float*  s_stg  = (float*) (smem + OFFB_STG);
    __half* s_kvh  = (__half*)(smem + OFFB_KV16);
    __half* s_wkh  = (__half*)(smem + OFFB_WK16);
    float*  s_qba  = (float*) (smem + OFFB_QBA);
    float*  s_qt   = (float*) (smem + OFFB_QT);
    float*  s_ws   = (float*) (smem + OFFB_WS);
    float*  s_sc   = (float*) (smem + OFFB_SC);
    __half* s_w16  = (__half*)(smem + OFFB_W16);   // [16][STRW]
    float*  s_wv   = (float*) (smem + OFFB_WV);
    float*  s_bs   = (float*) (smem + OFFB_BS);

    const int tid  = threadIdx.x;
    const int lane = tid & 31;
    const int wrp  = tid >> 5;       // warp's head (scores/softmax)
    const int g    = lane >> 2;
    const int tg   = lane & 3;

    const int bt0  = blockIdx.x;
    const int grid = gridDim.x;
    int ntiles = (BT - bt0 + grid - 1) / grid;
    if (ntiles > MAXT) ntiles = MAXT;
    if (ntiles < 1) return;

    prefetch_kv(kv_x + (size_t)bt0 * (NKEY * DK), s_stg);
    CP_COMMIT();

    // ---- one-time staging ----
    {
        #pragma unroll 1
        for (int j = tid; j < DOUT * 16; j += TPB) {
            int row = j >> 4, c4 = (j & 15) * 4;
            float4 v = __ldg((const float4*)(Wk + row * DK + c4));
            uint2 hh = make_uint2(f2h2(v.x, v.y), f2h2(v.z, v.w));
            *(uint2*)(s_wkh + row * STRH + c4) = hh;
        }
        if (tid < DK) s_ws[tid] = Ws[tid];
        if (tid == 0) s_bs[0] = bs[0];
        if (tid < 16) {   // zero kv row 127 once
            uint2 z = make_uint2(0u, 0u);
            *(uint2*)(s_kvh + 127 * STRH + tid * 4) = z;
        }
        for (int j = tid; j < 16 * STRW / 2; j += TPB)   // zero s_w16
            ((uint32_t*)s_w16)[j] = 0u;
        for (int idx = tid; idx < ntiles * DK; idx += TPB) {
            int t = idx >> 6, k = idx & 63;
            s_qt[t * DK + k] = q_x[(size_t)(bt0 + t * grid) * DK + k];
        }
    }
    __syncthreads();

    // ---- prologue: qb for every tile; thread covers o = tid, tid+128 ----
    #pragma unroll 1
    for (int rep = 0; rep < 2; ++rep) {
        const int o = tid + rep * 128;
        float4 wq[16];
        const float4* wq4 = (const float4*)(Wq + o * DK);
        #pragma unroll
        for (int i = 0; i < 16; i++) wq[i] = __ldg(wq4 + i);
        const float bb = __ldg(bias + (o & (DK - 1)));
        #pragma unroll 1
        for (int t = 0; t < ntiles; ++t) {
            const float* qq = s_qt + t * DK;
            float a0 = 0.f, a1 = 0.f, a2 = 0.f, a3 = 0.f;
            #pragma unroll
            for (int i = 0; i < 16; i++) {
                a0 = fmaf(qq[4 * i + 0], wq[i].x, a0);
                a1 = fmaf(qq[4 * i + 1], wq[i].y, a1);
                a2 = fmaf(qq[4 * i + 2], wq[i].z, a2);
                a3 = fmaf(qq[4 * i + 3], wq[i].w, a3);
            }
            s_qba[t * DOUT + o] = (a0 + a1) + (a2 + a3) + bb;
        }
    }

    int ti = 0;
    for (int bt = bt0; bt < BT; bt += grid, ++ti) {
        CP_WAIT0();
        __syncthreads();           // staging ready; prior tile consumed

        // ---- convert staging -> fp16 kv ----
        if (tid < NKEY) {
            const float* src = s_stg + tid * STGF;
            __half* dst = s_kvh + tid * STRH;
            #pragma unroll
            for (int u = 0; u < 16; ++u) {
                float4 v = *(const float4*)(src + u * 4);
                uint2 hh = make_uint2(f2h2(v.x, v.y), f2h2(v.z, v.w));
                *(uint2*)(dst + u * 4) = hh;
            }
        }
        __syncthreads();           // kv16 ready; staging free

        int bt_next = bt + grid;
        if (bt_next < BT) {
            prefetch_kv(kv_x + (size_t)bt_next * (NKEY * DK), s_stg);
            CP_COMMIT();
        }

        const float* qbt = s_qba + ti * DOUT;
        const float  bsv = s_bs[0];
        const int head = wrp;
        const __half* wkp = s_wkh + (head * 64) * STRH;

        // ---- score GEMM: fp16 m16n8k16; warp = head, 4 nh tasks ----
        #pragma unroll 1
        for (int nh = 0; nh < 4; ++nh) {
            const __half* kvp = s_kvh + (nh * 32) * STRH;

            float acc[2][8][4];
            #pragma unroll
            for (int mb = 0; mb < 2; ++mb)
                #pragma unroll
                for (int nb = 0; nb < 8; ++nb)
                    #pragma unroll
                    for (int c = 0; c < 4; ++c) acc[mb][nb][c] = 0.f;

            #pragma unroll
            for (int kc = 0; kc < 4; ++kc) {
                const int ho = kc * 16 + 4 * tg;   // permuted k slots
                uint2 u[2], v[2];
                #pragma unroll
                for (int mb = 0; mb < 2; ++mb) {
                    const __half* ar = kvp + (mb * 16 + g) * STRH + ho;
                    u[mb] = *(const uint2*)ar;
                    v[mb] = *(const uint2*)(ar + 8 * STRH);
                }
                #pragma unroll
                for (int nb = 0; nb < 8; ++nb) {
                    uint2 w = *(const uint2*)(wkp + (nb * 8 + g) * STRH + ho);
                    #pragma unroll
                    for (int mb = 0; mb < 2; ++mb)
                        mma16(acc[mb][nb][0], acc[mb][nb][1],
                              acc[mb][nb][2], acc[mb][nb][3],
                              u[mb].x, v[mb].x, u[mb].y, v[mb].y,
                              w.x, w.y);
                }
            }

            // epilogue: tanh + Ws reduction over this head's 64 o
            float part[2][2];
            part[0][0] = part[0][1] = part[1][0] = part[1][1] = 0.f;
            #pragma unroll
            for (int nb = 0; nb < 8; ++nb) {
                #pragma unroll
                for (int cc = 0; cc < 2; ++cc) {
                    const int k = nb * 8 + tg * 2 + cc;
                    const float wsk = s_ws[k];
                    const float qbo = qbt[head * 64 + k];
                    #pragma unroll
                    for (int mb = 0; mb < 2; ++mb) {
                        part[mb][0] = fmaf(
                            wsk, tanh_fast(acc[mb][nb][cc] + qbo),
                            part[mb][0]);
                        part[mb][1] = fmaf(
                            wsk, tanh_fast(acc[mb][nb][2 + cc] + qbo),
                            part[mb][1]);
                    }
                }
            }
            #pragma unroll
            for (int m = 1; m <= 2; m <<= 1) {
                #pragma unroll
                for (int mb = 0; mb < 2; ++mb) {
                    part[mb][0] += __shfl_xor_sync(0xffffffffu, part[mb][0], m);
                    part[mb][1] += __shfl_xor_sync(0xffffffffu, part[mb][1], m);
                }
            }
            if (tg == 0) {
                #pragma unroll
                for (int mb = 0; mb < 2; ++mb) {
                    const int r = nh * 32 + mb * 16 + g;
                    s_sc[head * 128 + r]     = part[mb][0] + bsv;
                    s_sc[head * 128 + r + 8] = part[mb][1] + bsv;
                }
            }
        }
        __syncwarp();              // s_sc produced/consumed by same warp

        // ---- softmax per head (warp per head) -> fp16 w row ----
        {
            int hh = wrp;
            int ln = lane;
            const float* sc = s_sc + hh * 128;
            float v0 = sc[ln];
            float v1 = sc[ln + 32];
            float v2 = sc[ln + 64];
            float v3 = (ln + 96 < NKEY) ? sc[ln + 96] : -1e30f;
            float m = fmaxf(fmaxf(v0, v1), fmaxf(v2, v3));
            #pragma unroll
            for (int o = 16; o > 0; o >>= 1)
                m = fmaxf(m, __shfl_xor_sync(0xffffffffu, m, o));
            float e0 = __expf(v0 - m);
            float e1 = __expf(v1 - m);
            float e2 = __expf(v2 - m);
            float e3 = (ln + 96 < NKEY) ? __expf(v3 - m) : 0.f;
            float s = (e0 + e1) + (e2 + e3);
            #pragma unroll
            for (int o = 16; o > 0; o >>= 1)
                s += __shfl_xor_sync(0xffffffffu, s, o);
            float inv = 1.f / s;
            __half* wr = s_w16 + hh * STRW;
            wr[ln]      = __float2half(e0 * inv);
            wr[ln + 32] = __float2half(e1 * inv);
            wr[ln + 64] = __float2half(e2 * inv);
            wr[ln + 96] = (ln + 96 < NKEY) ? __float2half(e3 * inv)
                                           : __half(0.f);
        }
        __syncthreads();           // all 4 w rows ready for PV MMA

        // ---- P·V via tensor cores: warp owns 16 cols ----
        {
            const int c0 = wrp * 16;
            float pv[2][4];
            #pragma unroll
            for (int cc = 0; cc < 2; ++cc)
                #pragma unroll
                for (int c = 0; c < 4; ++c) pv[cc][c] = 0.f;

            #pragma unroll
            for (int kc = 0; kc < 8; ++kc) {
                const int k0 = kc * 16;
                uint32_t a0 = *(const uint32_t*)(s_w16 + g * STRW + k0 + 2 * tg);
                uint32_t a1 = *(const uint32_t*)(s_w16 + (g + 8) * STRW + k0 + 2 * tg);
                uint32_t a2 = *(const uint32_t*)(s_w16 + g * STRW + k0 + 8 + 2 * tg);
                uint32_t a3 = *(const uint32_t*)(s_w16 + (g + 8) * STRW + k0 + 8 + 2 * tg);
                #pragma unroll
                for (int cc = 0; cc < 2; ++cc) {
                    uint32_t baddr = (uint32_t)__cvta_generic_to_shared(
                        s_kvh + (k0 + (lane & 15)) * STRH + c0 + cc * 8);
                    uint32_t b0, b1;
                    ldmx2t(b0, b1, baddr);
                    mma16(pv[cc][0], pv[cc][1], pv[cc][2], pv[cc][3],
                          a0, a1, a2, a3, b0, b1);
                }
            }
            if (g < NH) {
                #pragma unroll
                for (int cc = 0; cc < 2; ++cc) {
                    s_wv[g * 64 + c0 + cc * 8 + 2 * tg]     = pv[cc][0];
                    s_wv[g * 64 + c0 + cc * 8 + 2 * tg + 1] = pv[cc][1];
                }
            }
        }
        __syncthreads();           // wv ready

        // ---- output projection: thread covers o = tid, tid+128 ----
        #pragma unroll 1
        for (int rep = 0; rep < 2; ++rep) {
            const int o = tid + rep * 128;
            const float* wvh = s_wv + (o >> 6) * 64;
            const float4* wv4 = (const float4*)(Wv + o * DK);
            float a0 = 0.f, a1 = 0.f, a2 = 0.f, a3 = 0.f;
            #pragma unroll
            for (int i = 0; i < 16; i++) {
                float4 w = __ldg(wv4 + i);
                a0 = fmaf(wvh[4 * i + 0], w.x, a0);
                a1 = fmaf(wvh[4 * i + 1], w.y, a1);
                a2 = fmaf(wvh[4 * i + 2], w.z, a2);
                a3 = fmaf(wvh[4 * i + 3], w.w, a3);
            }
            out[(size_t)bt * DOUT + o] = (a0 + a1) + (a2 + a3);
        }
    }
}

extern "C" void kernel_launch(void* const* d_in, const int* in_sizes, int n_in,
                              void* d_out, int out_size) {
    (void)n_in; (void)out_size;
    const float* q_x  = (const float*)d_in[0];
    const float* kv_x = (const float*)d_in[1];
    const float* Wk   = (const float*)d_in[2];
    const float* Wq   = (const float*)d_in[3];
    const float* Wv   = (const float*)d_in[4];
    const float* bias = (const float*)d_in[5];
    const float* Ws   = (const float*)d_in[6];
    const float* bs   = (const float*)d_in[7];
    float* out = (float*)d_out;

    const int BT = in_sizes[0] / DK;
    int grid = 2 * 152;
    if (grid > BT) grid = BT;
    while ((BT + grid - 1) / grid > MAXT) grid += 2 * 152;

    cudaFuncSetAttribute(raamh_kernel,
                         cudaFuncAttributeMaxDynamicSharedMemorySize,
                         SMEM_BYTES);
    raamh_kernel<<<grid, TPB, SMEM_BYTES>>>(q_x, kv_x, Wk, Wq, Wv,
                                            bias, Ws, bs, out, BT);
}